// round 2
// baseline (speedup 1.0000x reference)
#include <cuda_runtime.h>
#include <cuda_bf16.h>
#include <math.h>

// Problem constants
#define VOCAB   100000
#define EMBED   300
#define HIDDEN  300
#define BATCH   32768
#define K_NEG   10
#define EPS_F   1e-5f

// GEMM tiling
#define GM 128
#define GN 128
#define GK 16

// Kernel C config
#define CW_BLOCK 256
#define CW_WARPS (CW_BLOCK/32)
#define NPART    (BATCH / CW_WARPS)   // 4096 partial blocks

// Scratch (device globals; allocation is forbidden)
__device__ float g_enc[BATCH * HIDDEN];
__device__ float g_cv [BATCH * EMBED];
__device__ float g_partial[NPART * 2];

// ---------------------------------------------------------------------------
// Tiled NT GEMM: C[M,N] = gather(A)[M,K] * W[N,K]^T + bias[N]
// A rows optionally gathered through gatherIdx. 128x128 tile, 8x8 per thread.
// ---------------------------------------------------------------------------
__global__ __launch_bounds__(256, 2)
void gemm_nt_kernel(const float* __restrict__ Abase,
                    const int*   __restrict__ gatherIdx,
                    const float* __restrict__ W,
                    const float* __restrict__ bias,
                    float* __restrict__ C,
                    int M, int N, int K)
{
    __shared__ float sA[GK][GM];
    __shared__ float sB[GK][GN];

    const int tid = threadIdx.x;
    const int tx  = tid & 15;        // 0..15  -> N direction
    const int ty  = tid >> 4;        // 0..15  -> M direction
    const int bm  = blockIdx.y * GM;
    const int bn  = blockIdx.x * GN;

    float acc[8][8];
#pragma unroll
    for (int i = 0; i < 8; i++)
#pragma unroll
        for (int j = 0; j < 8; j++) acc[i][j] = 0.f;

    // loader mapping: each thread loads 8 consecutive k for one row
    const int l_row = tid >> 1;          // 0..127
    const int l_k0  = (tid & 1) * 8;     // 0 or 8

    // resolve A source row pointer once (gather)
    const float* arow = nullptr;
    {
        int m = bm + l_row;
        if (m < M) {
            long src = gatherIdx ? (long)gatherIdx[m] : (long)m;
            arow = Abase + src * (long)K;
        }
    }
    const float* wrow = nullptr;
    {
        int n = bn + l_row;
        if (n < N) wrow = W + (long)n * (long)K;
    }

    for (int k0 = 0; k0 < K; k0 += GK) {
#pragma unroll
        for (int i = 0; i < 8; i++) {
            int k = k0 + l_k0 + i;
            sA[l_k0 + i][l_row] = (arow != nullptr && k < K) ? arow[k] : 0.f;
        }
#pragma unroll
        for (int i = 0; i < 8; i++) {
            int k = k0 + l_k0 + i;
            sB[l_k0 + i][l_row] = (wrow != nullptr && k < K) ? wrow[k] : 0.f;
        }
        __syncthreads();

#pragma unroll
        for (int kk = 0; kk < GK; kk++) {
            float a[8], b[8];
#pragma unroll
            for (int i = 0; i < 8; i++) a[i] = sA[kk][ty * 8 + i];
#pragma unroll
            for (int j = 0; j < 8; j++) b[j] = sB[kk][tx * 8 + j];
#pragma unroll
            for (int i = 0; i < 8; i++)
#pragma unroll
                for (int j = 0; j < 8; j++)
                    acc[i][j] = fmaf(a[i], b[j], acc[i][j]);
        }
        __syncthreads();
    }

#pragma unroll
    for (int i = 0; i < 8; i++) {
        int m = bm + ty * 8 + i;
        if (m >= M) continue;
#pragma unroll
        for (int j = 0; j < 8; j++) {
            int n = bn + tx * 8 + j;
            if (n < N) C[(long)m * N + n] = acc[i][j] + bias[n];
        }
    }
}

// ---------------------------------------------------------------------------
// stable softplus: log(1+exp(x)), |x| <= ~10 in practice but keep it stable
// ---------------------------------------------------------------------------
__device__ __forceinline__ float softplus_f(float x) {
    float ax = fabsf(x);
    float r = log1pf(__expf(-ax));
    return (x > 0.f) ? x + r : r;
}

__device__ __forceinline__ float clip10(float x) {
    return fminf(fmaxf(x, -10.f), 10.f);
}

__device__ __forceinline__ float warp_sum(float v) {
#pragma unroll
    for (int o = 16; o > 0; o >>= 1) v += __shfl_xor_sync(0xffffffffu, v, o);
    return v;
}

// ---------------------------------------------------------------------------
// Kernel C: one warp per sample. Computes deno per-sample loss (pos + 10 neg
// softplus terms) and cono NLL; block-reduces into g_partial (deterministic).
// ---------------------------------------------------------------------------
__global__ __launch_bounds__(CW_BLOCK)
void score_kernel(const int*   __restrict__ ctx_ids,
                  const int*   __restrict__ neg_ids,
                  const int*   __restrict__ party,
                  const float* __restrict__ ctx_emb,
                  const float* __restrict__ W_cls,
                  const float* __restrict__ b_cls)
{
    const int warp = threadIdx.x >> 5;
    const int lane = threadIdx.x & 31;
    const int b    = blockIdx.x * CW_WARPS + warp;

    __shared__ float s_deno[CW_WARPS];
    __shared__ float s_cono[CW_WARPS];

    // load center_v[b] into registers, lane-strided over e
    float cv[10];
#pragma unroll
    for (int j = 0; j < 10; j++) {
        int e = lane + j * 32;
        cv[j] = (e < EMBED) ? g_cv[(long)b * EMBED + e] : 0.f;
    }

    // positive context dot
    float deno;
    {
        long cid = (long)ctx_ids[b];
        const float* row = ctx_emb + cid * EMBED;
        float s = 0.f;
#pragma unroll
        for (int j = 0; j < 10; j++) {
            int e = lane + j * 32;
            if (e < EMBED) s = fmaf(cv[j], row[e], s);
        }
        s = warp_sum(s);
        deno = softplus_f(-clip10(s));   // -logsigmoid(pos_score)
    }

    // negative contexts
#pragma unroll 1
    for (int k = 0; k < K_NEG; k++) {
        long nid = (long)neg_ids[(long)b * K_NEG + k];
        const float* row = ctx_emb + nid * EMBED;
        float s = 0.f;
#pragma unroll
        for (int j = 0; j < 10; j++) {
            int e = lane + j * 32;
            if (e < EMBED) s = fmaf(cv[j], row[e], s);
        }
        s = warp_sum(s);
        deno += softplus_f(clip10(s));   // -logsigmoid(-neg_score)
    }

    // cono: logits = enc[b] . W_cls[c] + b_cls[c], c in {0,1}; 2-class CE
    float l0 = 0.f, l1 = 0.f;
#pragma unroll
    for (int j = 0; j < 10; j++) {
        int e = lane + j * 32;
        if (e < HIDDEN) {
            float h = g_enc[(long)b * HIDDEN + e];
            l0 = fmaf(h, W_cls[e], l0);
            l1 = fmaf(h, W_cls[HIDDEN + e], l1);
        }
    }
    l0 = warp_sum(l0) + b_cls[0];
    l1 = warp_sum(l1) + b_cls[1];
    int lab = party[b];
    float diff = (lab == 0) ? (l1 - l0) : (l0 - l1);
    float nll = softplus_f(diff);        // logsumexp - l_label for 2 classes

    if (lane == 0) { s_deno[warp] = deno; s_cono[warp] = nll; }
    __syncthreads();
    if (threadIdx.x == 0) {
        float ds = 0.f, cs = 0.f;
#pragma unroll
        for (int w = 0; w < CW_WARPS; w++) { ds += s_deno[w]; cs += s_cono[w]; }
        g_partial[blockIdx.x * 2 + 0] = ds;
        g_partial[blockIdx.x * 2 + 1] = cs;
    }
}

// ---------------------------------------------------------------------------
// Finalize: reduce partials, means, clips, write 3 outputs
// ---------------------------------------------------------------------------
__global__ void finalize_kernel(float* __restrict__ out)
{
    __shared__ float sd[256];
    __shared__ float sc[256];
    float d = 0.f, c = 0.f;
    for (int i = threadIdx.x; i < NPART; i += 256) {
        d += g_partial[i * 2 + 0];
        c += g_partial[i * 2 + 1];
    }
    sd[threadIdx.x] = d; sc[threadIdx.x] = c;
    __syncthreads();
    for (int s = 128; s > 0; s >>= 1) {
        if (threadIdx.x < s) {
            sd[threadIdx.x] += sd[threadIdx.x + s];
            sc[threadIdx.x] += sc[threadIdx.x + s];
        }
        __syncthreads();
    }
    if (threadIdx.x == 0) {
        float deno = sd[0] / (float)BATCH;
        float cono = sc[0] / (float)BATCH;
        deno = fminf(fmaxf(deno, EPS_F), 10.f);
        cono = fminf(fmaxf(cono, EPS_F), 10.f);
        float encl = fmaxf(deno + cono, EPS_F);
        out[0] = encl;
        out[1] = deno;
        out[2] = cono;
    }
}

// ---------------------------------------------------------------------------
// kernel_launch
// input order (metadata): 0 center_word_ids, 1 context_word_ids,
// 2 neg_context_ids, 3 party_label, 4 center_emb, 5 context_emb,
// 6 W_enc, 7 b_enc, 8 W_dec, 9 b_dec, 10 W_cls, 11 b_cls
// ---------------------------------------------------------------------------
extern "C" void kernel_launch(void* const* d_in, const int* in_sizes, int n_in,
                              void* d_out, int out_size)
{
    const int*   center_ids = (const int*)  d_in[0];
    const int*   ctx_ids    = (const int*)  d_in[1];
    const int*   neg_ids    = (const int*)  d_in[2];
    const int*   party      = (const int*)  d_in[3];
    const float* center_emb = (const float*)d_in[4];
    const float* ctx_emb    = (const float*)d_in[5];
    const float* W_enc      = (const float*)d_in[6];
    const float* b_enc      = (const float*)d_in[7];
    const float* W_dec      = (const float*)d_in[8];
    const float* b_dec      = (const float*)d_in[9];
    const float* W_cls      = (const float*)d_in[10];
    const float* b_cls      = (const float*)d_in[11];
    float* out = (float*)d_out;

    float* enc_ptr; cudaGetSymbolAddress((void**)&enc_ptr, g_enc);
    float* cv_ptr;  cudaGetSymbolAddress((void**)&cv_ptr,  g_cv);

    // GEMM1: enc[B,H] = center_emb[gather][B,E] @ W_enc[H,E]^T + b_enc
    {
        dim3 grid((HIDDEN + GN - 1) / GN, BATCH / GM);
        gemm_nt_kernel<<<grid, 256>>>(center_emb, center_ids, W_enc, b_enc,
                                      enc_ptr, BATCH, HIDDEN, EMBED);
    }
    // GEMM2: center_v[B,E] = enc[B,H] @ W_dec[E,H]^T + b_dec
    {
        dim3 grid((EMBED + GN - 1) / GN, BATCH / GM);
        gemm_nt_kernel<<<grid, 256>>>(enc_ptr, nullptr, W_dec, b_dec,
                                      cv_ptr, BATCH, EMBED, HIDDEN);
    }
    // Per-sample scoring + partial sums
    score_kernel<<<NPART, CW_BLOCK>>>(ctx_ids, neg_ids, party,
                                      ctx_emb, W_cls, b_cls);
    // Final reduction
    finalize_kernel<<<1, 256>>>(out);
}

// round 7
// speedup vs baseline: 3.5694x; 3.5694x over previous
#include <cuda_runtime.h>
#include <cuda_bf16.h>
#include <math.h>
#include <stdint.h>

// ---------------- problem constants ----------------
#define VOCAB   100000
#define EMBED   300
#define HIDDEN  300
#define BATCH   32768
#define K_NEG   10
#define EPS_F   1e-5f

// ---------------- GEMM geometry ----------------
#define MTILE    128
#define MTILES   (BATCH / MTILE)        // 256
#define NSPLIT   5                      // N padded to 320, 64 per split
#define NCHK     5                      // K padded to 320, 64 per chunk
#define A_CHT_B  16384                  // A chunk tile: 128 rows * 128 B
#define A_CHT_I4 1024
#define B_CHT_B  8192                   // B chunk tile: 64 rows * 128 B
#define B_CHT_I4 512

// ---------------- scratch (device globals; no allocation allowed) ----------------
__device__ int4  g_a1[MTILES * NCHK * A_CHT_I4];   // gathered center_emb, bf16 swizzled
__device__ int4  g_a2[MTILES * NCHK * A_CHT_I4];   // enc, bf16 swizzled (GEMM1 epilogue)
__device__ int4  g_w1[NSPLIT * NCHK * B_CHT_I4];   // [W_enc; W_cls; 0] bf16 swizzled
__device__ int4  g_w2[NSPLIT * NCHK * B_CHT_I4];   // [W_dec; 0] bf16 swizzled
__device__ float g_logits[BATCH * 2];
__device__ float g_cv[BATCH * EMBED];
#define NPART 4096
__device__ float g_partial[NPART * 2];

// ---------------- small device helpers ----------------
__device__ __forceinline__ uint32_t swz(uint32_t o) { return o ^ ((o >> 3) & 0x70); }

__device__ __forceinline__ uint32_t smem_u32(const void* p) {
    uint32_t a;
    asm("{ .reg .u64 t; cvta.to.shared.u64 t, %1; cvt.u32.u64 %0, t; }" : "=r"(a) : "l"(p));
    return a;
}
__device__ __forceinline__ void ldm_x4(uint32_t* r, uint32_t addr) {
    asm volatile("ldmatrix.sync.aligned.m8n8.x4.shared.b16 {%0,%1,%2,%3}, [%4];"
                 : "=r"(r[0]), "=r"(r[1]), "=r"(r[2]), "=r"(r[3]) : "r"(addr));
}
__device__ __forceinline__ void ldm_x2(uint32_t* r, uint32_t addr) {
    asm volatile("ldmatrix.sync.aligned.m8n8.x2.shared.b16 {%0,%1}, [%2];"
                 : "=r"(r[0]), "=r"(r[1]) : "r"(addr));
}
__device__ __forceinline__ void mma_16816(float* c, const uint32_t* a, const uint32_t* b) {
    asm volatile("mma.sync.aligned.m16n8k16.row.col.f32.bf16.bf16.f32 "
                 "{%0,%1,%2,%3}, {%4,%5,%6,%7}, {%8,%9}, {%0,%1,%2,%3};"
                 : "+f"(c[0]), "+f"(c[1]), "+f"(c[2]), "+f"(c[3])
                 : "r"(a[0]), "r"(a[1]), "r"(a[2]), "r"(a[3]), "r"(b[0]), "r"(b[1]));
}

// ---------------------------------------------------------------------------
// Prepass A: gather center_emb rows, convert bf16, write swizzled chunk layout
// tile (mt, ch): 128 rows x 64 cols (16KB), SW128 swizzle inside tile
// ---------------------------------------------------------------------------
__global__ __launch_bounds__(256)
void conv_a_kernel(const float* __restrict__ emb, const int* __restrict__ ids)
{
    const int total = BATCH * 320;
    for (int idx = blockIdx.x * blockDim.x + threadIdx.x; idx < total;
         idx += gridDim.x * blockDim.x) {
        int m = idx / 320;
        int k = idx - m * 320;
        float v = 0.f;
        if (k < EMBED) v = emb[(long)ids[m] * EMBED + k];
        int mt = m >> 7, mrow = m & 127, ch = k >> 6, col = k & 63;
        char* base = (char*)g_a1 + (size_t)(mt * NCHK + ch) * A_CHT_B;
        *(__nv_bfloat16*)(base + swz((uint32_t)(mrow * 128 + col * 2))) = __float2bfloat16(v);
    }
}

// ---------------------------------------------------------------------------
// Prepass W: convert weights into swizzled 64x64 chunk tiles.
// mode 1: rows 0..299 = W_enc, 300..301 = W_cls, rest zero
// mode 2: rows 0..299 = W_dec, rest zero; cols >= 300 zero in both
// ---------------------------------------------------------------------------
__global__ __launch_bounds__(256)
void conv_w_kernel(const float* __restrict__ W, const float* __restrict__ Wcls, int mode)
{
    const int total = NSPLIT * NCHK * 64 * 64;   // 102400
    int idx = blockIdx.x * blockDim.x + threadIdx.x;
    if (idx >= total) return;
    int col = idx & 63;
    int r   = (idx >> 6) & 63;
    int c   = (idx >> 12) % NCHK;
    int s   = idx / (4096 * NCHK);
    int n = s * 64 + r;
    int k = c * 64 + col;
    float v = 0.f;
    if (k < 300) {
        if (n < 300)                   v = W[n * 300 + k];
        else if (mode == 1 && n < 302) v = Wcls[(n - 300) * 300 + k];
    }
    int4* gw = (mode == 1) ? g_w1 : g_w2;
    char* base = (char*)gw + (size_t)(s * NCHK + c) * B_CHT_B;
    *(__nv_bfloat16*)(base + swz((uint32_t)(r * 128 + col * 2))) = __float2bfloat16(v);
}

// ---------------------------------------------------------------------------
// bf16 HMMA GEMM: C[128, 64] tile = A[128, 320] @ W[64, 320]^T  (K in 5 chunks)
// 8 warps, warp tile 32x32 (2 m-frags x 4 n-frags of m16n8k16).
// mode 1: epilogue -> g_a2 (bf16 swizzled A-layout) + g_logits (+b_cls)
// mode 2: epilogue -> g_cv f32 (+b_dec)
// ---------------------------------------------------------------------------
__global__ __launch_bounds__(256)
void gemm_kernel(const int4* __restrict__ A, const int4* __restrict__ B,
                 const float* __restrict__ bias, const float* __restrict__ bias2,
                 int mode)
{
    __shared__ int4 sA[A_CHT_I4];   // 16 KB
    __shared__ int4 sB[B_CHT_I4];   // 8 KB

    const int tid  = threadIdx.x;
    const int wid  = tid >> 5;
    const int lane = tid & 31;
    const int mt = blockIdx.y;
    const int ns = blockIdx.x;
    const int mw = wid & 3;          // M quarter (32 rows)
    const int nw = wid >> 2;         // N half (32 cols)

    const uint32_t sAb = smem_u32(sA);
    const uint32_t sBb = smem_u32(sB);

    float acc[2][4][4];
#pragma unroll
    for (int i = 0; i < 2; i++)
#pragma unroll
        for (int j = 0; j < 4; j++)
#pragma unroll
            for (int q = 0; q < 4; q++) acc[i][j][q] = 0.f;

    const int4* Abase = A + (size_t)mt * NCHK * A_CHT_I4;
    const int4* Bbase = B + (size_t)ns * NCHK * B_CHT_I4;

    // precomputed ldmatrix address components
    const uint32_t a_row = mw * 32 + (lane & 15);
    const uint32_t a_kb  = (lane >> 4) * 16;          // bytes
    const uint32_t b_row0 = nw * 32 + (lane & 7);
    const uint32_t b_kb  = ((lane >> 3) & 1) * 16;    // bytes

    for (int c = 0; c < NCHK; c++) {
        const int4* as = Abase + c * A_CHT_I4;
#pragma unroll
        for (int i = 0; i < 4; i++) sA[tid + i * 256] = as[tid + i * 256];
        const int4* bs = Bbase + c * B_CHT_I4;
#pragma unroll
        for (int i = 0; i < 2; i++) sB[tid + i * 256] = bs[tid + i * 256];
        __syncthreads();

#pragma unroll
        for (int ks = 0; ks < 4; ks++) {
            const uint32_t kb = ks * 32;   // 16 bf16 = 32 bytes
            uint32_t a[2][4];
#pragma unroll
            for (int fm = 0; fm < 2; fm++)
                ldm_x4(a[fm], sAb + swz((a_row + fm * 16) * 128 + kb + a_kb));
#pragma unroll
            for (int fn = 0; fn < 4; fn++) {
                uint32_t b[2];
                ldm_x2(b, sBb + swz((b_row0 + fn * 8) * 128 + kb + b_kb));
                mma_16816(acc[0][fn], a[0], b);
                mma_16816(acc[1][fn], a[1], b);
            }
        }
        __syncthreads();
    }

    // ---- epilogue ----
#pragma unroll
    for (int fm = 0; fm < 2; fm++) {
#pragma unroll
        for (int fn = 0; fn < 4; fn++) {
            const int n = ns * 64 + nw * 32 + fn * 8 + 2 * (lane & 3);
#pragma unroll
            for (int half = 0; half < 2; half++) {
                const int mrow = mw * 32 + fm * 16 + (lane >> 2) + half * 8;
                const long m = (long)mt * MTILE + mrow;
                float v0 = acc[fm][fn][half * 2 + 0];
                float v1 = acc[fm][fn][half * 2 + 1];
                if (mode == 1) {
                    float b0 = (n < 300) ? bias[n] : ((n == 300) ? bias2[0] : 0.f);
                    float b1 = (n + 1 < 300) ? bias[n + 1] : ((n + 1 == 301) ? bias2[1] : 0.f);
                    v0 += b0; v1 += b1;
                    if (n == 300) {
                        g_logits[m * 2 + 0] = v0;
                        g_logits[m * 2 + 1] = v1;
                    }
                    __nv_bfloat162 h = __floats2bfloat162_rn(v0, v1);
                    char* dst = (char*)g_a2 + (size_t)(mt * NCHK + ns) * A_CHT_B
                                + swz((uint32_t)(mrow * 128 + (n & 63) * 2));
                    *(__nv_bfloat162*)dst = h;
                } else {
                    if (n < 300) {  // n even => n <= 298, n+1 <= 299
                        v0 += bias[n];
                        v1 += bias[n + 1];
                        *(float2*)(g_cv + m * EMBED + n) = make_float2(v0, v1);
                    }
                }
            }
        }
    }
}

// ---------------------------------------------------------------------------
// math helpers
// ---------------------------------------------------------------------------
__device__ __forceinline__ float softplus_f(float x) {
    float ax = fabsf(x);
    float r = log1pf(__expf(-ax));
    return (x > 0.f) ? x + r : r;
}
__device__ __forceinline__ float clip10(float x) { return fminf(fmaxf(x, -10.f), 10.f); }
__device__ __forceinline__ float warp_sum(float v) {
#pragma unroll
    for (int o = 16; o > 0; o >>= 1) v += __shfl_xor_sync(0xffffffffu, v, o);
    return v;
}

// ---------------------------------------------------------------------------
// Score: one warp per sample; deno dots + cono nll from precomputed logits.
// ---------------------------------------------------------------------------
__global__ __launch_bounds__(256)
void score_kernel(const int* __restrict__ ctx_ids,
                  const int* __restrict__ neg_ids,
                  const int* __restrict__ party,
                  const float* __restrict__ ctx_emb)
{
    const int warp = threadIdx.x >> 5;
    const int lane = threadIdx.x & 31;
    const int b    = blockIdx.x * 8 + warp;

    __shared__ float s_deno[8];
    __shared__ float s_cono[8];

    float2 cv[5];
    const float2* cvrow = (const float2*)(g_cv + (long)b * EMBED);
#pragma unroll
    for (int j = 0; j < 5; j++) {
        int e2 = lane + j * 32;
        cv[j] = (e2 < 150) ? cvrow[e2] : make_float2(0.f, 0.f);
    }

    float deno;
    {
        const float2* rr = (const float2*)(ctx_emb + (long)ctx_ids[b] * EMBED);
        float s = 0.f;
#pragma unroll
        for (int j = 0; j < 5; j++) {
            int e2 = lane + j * 32;
            if (e2 < 150) { float2 t = rr[e2]; s = fmaf(cv[j].x, t.x, fmaf(cv[j].y, t.y, s)); }
        }
        s = warp_sum(s);
        deno = softplus_f(-clip10(s));
    }
#pragma unroll 1
    for (int k = 0; k < K_NEG; k++) {
        const float2* rr = (const float2*)(ctx_emb + (long)neg_ids[b * K_NEG + k] * EMBED);
        float s = 0.f;
#pragma unroll
        for (int j = 0; j < 5; j++) {
            int e2 = lane + j * 32;
            if (e2 < 150) { float2 t = rr[e2]; s = fmaf(cv[j].x, t.x, fmaf(cv[j].y, t.y, s)); }
        }
        s = warp_sum(s);
        deno += softplus_f(clip10(s));
    }

    float l0 = g_logits[b * 2 + 0];
    float l1 = g_logits[b * 2 + 1];
    int lab = party[b];
    float nll = softplus_f((lab == 0) ? (l1 - l0) : (l0 - l1));

    if (lane == 0) { s_deno[warp] = deno; s_cono[warp] = nll; }
    __syncthreads();
    if (threadIdx.x == 0) {
        float ds = 0.f, cs = 0.f;
#pragma unroll
        for (int w = 0; w < 8; w++) { ds += s_deno[w]; cs += s_cono[w]; }
        g_partial[blockIdx.x * 2 + 0] = ds;
        g_partial[blockIdx.x * 2 + 1] = cs;
    }
}

// ---------------------------------------------------------------------------
// Finalize
// ---------------------------------------------------------------------------
__global__ __launch_bounds__(1024)
void finalize_kernel(float* __restrict__ out)
{
    __shared__ float sd[1024];
    __shared__ float sc[1024];
    float d = 0.f, c = 0.f;
    for (int i = threadIdx.x; i < NPART; i += 1024) {
        d += g_partial[i * 2 + 0];
        c += g_partial[i * 2 + 1];
    }
    sd[threadIdx.x] = d; sc[threadIdx.x] = c;
    __syncthreads();
    for (int s = 512; s > 0; s >>= 1) {
        if (threadIdx.x < s) {
            sd[threadIdx.x] += sd[threadIdx.x + s];
            sc[threadIdx.x] += sc[threadIdx.x + s];
        }
        __syncthreads();
    }
    if (threadIdx.x == 0) {
        float deno = sd[0] / (float)BATCH;
        float cono = sc[0] / (float)BATCH;
        deno = fminf(fmaxf(deno, EPS_F), 10.f);
        cono = fminf(fmaxf(cono, EPS_F), 10.f);
        out[0] = fmaxf(deno + cono, EPS_F);
        out[1] = deno;
        out[2] = cono;
    }
}

// ---------------------------------------------------------------------------
// kernel_launch
// ---------------------------------------------------------------------------
extern "C" void kernel_launch(void* const* d_in, const int* in_sizes, int n_in,
                              void* d_out, int out_size)
{
    const int*   center_ids = (const int*)  d_in[0];
    const int*   ctx_ids    = (const int*)  d_in[1];
    const int*   neg_ids    = (const int*)  d_in[2];
    const int*   party      = (const int*)  d_in[3];
    const float* center_emb = (const float*)d_in[4];
    const float* ctx_emb    = (const float*)d_in[5];
    const float* W_enc      = (const float*)d_in[6];
    const float* b_enc      = (const float*)d_in[7];
    const float* W_dec      = (const float*)d_in[8];
    const float* b_dec      = (const float*)d_in[9];
    const float* W_cls      = (const float*)d_in[10];
    const float* b_cls      = (const float*)d_in[11];
    float* out = (float*)d_out;

    int4 *a1, *a2, *w1, *w2;
    cudaGetSymbolAddress((void**)&a1, g_a1);
    cudaGetSymbolAddress((void**)&a2, g_a2);
    cudaGetSymbolAddress((void**)&w1, g_w1);
    cudaGetSymbolAddress((void**)&w2, g_w2);

    // prepass conversions
    conv_w_kernel<<<(NSPLIT * NCHK * 64 * 64 + 255) / 256, 256>>>(W_enc, W_cls, 1);
    conv_w_kernel<<<(NSPLIT * NCHK * 64 * 64 + 255) / 256, 256>>>(W_dec, nullptr, 2);
    conv_a_kernel<<<4096, 256>>>(center_emb, center_ids);

    // GEMM1: [enc | logits] = gather(center_emb) @ [W_enc; W_cls]^T
    gemm_kernel<<<dim3(NSPLIT, MTILES), 256>>>(a1, w1, b_enc, b_cls, 1);
    // GEMM2: cv = enc @ W_dec^T + b_dec
    gemm_kernel<<<dim3(NSPLIT, MTILES), 256>>>(a2, w2, b_dec, nullptr, 2);

    // scoring + reduction
    score_kernel<<<NPART, 256>>>(ctx_ids, neg_ids, party, ctx_emb);
    finalize_kernel<<<1, 1024>>>(out);
}

// round 9
// speedup vs baseline: 4.3312x; 1.2134x over previous
#include <cuda_runtime.h>
#include <cuda_bf16.h>
#include <math.h>
#include <stdint.h>

// ---------------- problem constants ----------------
#define VOCAB   100000
#define EMBED   300
#define HIDDEN  300
#define BATCH   32768
#define K_NEG   10
#define EPS_F   1e-5f

// ---------------- GEMM geometry ----------------
#define MTILE    128
#define MTILES   (BATCH / MTILE)        // 256
#define NSPLIT   5                      // N padded to 320, 64 per split
#define NCHK     5                      // K padded to 320, 64 per chunk
#define A_CHT_B  16384                  // A chunk tile: 128 rows * 128 B
#define A_CHT_I4 1024
#define B_CHT_B  8192                   // B chunk tile: 64 rows * 128 B
#define B_CHT_I4 512

// ---------------- scratch (device globals; no allocation allowed) ----------------
__device__ int4  g_a1[MTILES * NCHK * A_CHT_I4];   // gathered center_emb, bf16 swizzled
__device__ int4  g_a2[MTILES * NCHK * A_CHT_I4];   // enc, bf16 swizzled (GEMM1 epilogue)
__device__ int4  g_w1[NSPLIT * NCHK * B_CHT_I4];   // [W_enc; W_cls; 0] bf16 swizzled
__device__ int4  g_w2[NSPLIT * NCHK * B_CHT_I4];   // [W_dec; 0] bf16 swizzled
__device__ float g_logits[BATCH * 2];
__device__ float g_cv[BATCH * EMBED];
#define NPART 4096
__device__ float g_partial[NPART * 2];

// ---------------- small device helpers ----------------
__device__ __forceinline__ uint32_t swz(uint32_t o) { return o ^ ((o >> 3) & 0x70); }

__device__ __forceinline__ uint32_t smem_u32(const void* p) {
    uint32_t a;
    asm("{ .reg .u64 t; cvta.to.shared.u64 t, %1; cvt.u32.u64 %0, t; }" : "=r"(a) : "l"(p));
    return a;
}
__device__ __forceinline__ void ldm_x4(uint32_t* r, uint32_t addr) {
    asm volatile("ldmatrix.sync.aligned.m8n8.x4.shared.b16 {%0,%1,%2,%3}, [%4];"
                 : "=r"(r[0]), "=r"(r[1]), "=r"(r[2]), "=r"(r[3]) : "r"(addr));
}
__device__ __forceinline__ void mma_16816(float* c, const uint32_t* a, const uint32_t* b) {
    asm volatile("mma.sync.aligned.m16n8k16.row.col.f32.bf16.bf16.f32 "
                 "{%0,%1,%2,%3}, {%4,%5,%6,%7}, {%8,%9}, {%0,%1,%2,%3};"
                 : "+f"(c[0]), "+f"(c[1]), "+f"(c[2]), "+f"(c[3])
                 : "r"(a[0]), "r"(a[1]), "r"(a[2]), "r"(a[3]), "r"(b[0]), "r"(b[1]));
}
__device__ __forceinline__ void cp_async16(uint32_t dst, const void* src) {
    asm volatile("cp.async.cg.shared.global [%0], [%1], 16;" :: "r"(dst), "l"(src));
}
__device__ __forceinline__ void cp_commit() {
    asm volatile("cp.async.commit_group;" ::: "memory");
}
__device__ __forceinline__ void cp_wait1() {
    asm volatile("cp.async.wait_group 1;" ::: "memory");
}
__device__ __forceinline__ void cp_wait0() {
    asm volatile("cp.async.wait_group 0;" ::: "memory");
}

__device__ __forceinline__ int4 pack8_bf16(const float* v) {
    union { __nv_bfloat162 h[4]; int4 q; } u;
#pragma unroll
    for (int j = 0; j < 4; j++) u.h[j] = __floats2bfloat162_rn(v[2 * j], v[2 * j + 1]);
    return u.q;
}

// ---------------------------------------------------------------------------
// Prepass A: gather center_emb rows -> bf16 swizzled chunk tiles.
// One thread = 8 consecutive k (2x float4 load, 1x int4 swizzled store).
// ---------------------------------------------------------------------------
__global__ __launch_bounds__(256)
void conv_a_kernel(const float* __restrict__ emb, const int* __restrict__ ids)
{
    int idx = blockIdx.x * blockDim.x + threadIdx.x;   // BATCH*40 threads
    int m  = idx / 40;
    int g  = idx - m * 40;
    int k0 = g * 8;
    const float* row = emb + (long)ids[m] * EMBED;

    float v[8];
    if (k0 + 8 <= EMBED) {
        float4 f0 = *(const float4*)(row + k0);
        float4 f1 = *(const float4*)(row + k0 + 4);
        v[0]=f0.x; v[1]=f0.y; v[2]=f0.z; v[3]=f0.w;
        v[4]=f1.x; v[5]=f1.y; v[6]=f1.z; v[7]=f1.w;
    } else if (k0 < EMBED) {      // k0 == 296
        float4 f0 = *(const float4*)(row + k0);
        v[0]=f0.x; v[1]=f0.y; v[2]=f0.z; v[3]=f0.w;
        v[4]=v[5]=v[6]=v[7]=0.f;
    } else {
#pragma unroll
        for (int j = 0; j < 8; j++) v[j] = 0.f;
    }

    int mt = m >> 7, mrow = m & 127, ch = k0 >> 6, col0 = k0 & 63;
    char* base = (char*)g_a1 + (size_t)(mt * NCHK + ch) * A_CHT_B;
    *(int4*)(base + swz((uint32_t)(mrow * 128 + col0 * 2))) = pack8_bf16(v);
}

// ---------------------------------------------------------------------------
// Prepass W: both weight conversions in one launch (vectorized by 8).
// mode 0 (-> g_w1): rows 0..299 = W_enc, 300..301 = W_cls, rest 0
// mode 1 (-> g_w2): rows 0..299 = W_dec, rest 0
// ---------------------------------------------------------------------------
__global__ __launch_bounds__(256)
void conv_w_kernel(const float* __restrict__ Wenc, const float* __restrict__ Wcls,
                   const float* __restrict__ Wdec)
{
    const int PER_MODE = NSPLIT * NCHK * 64 * 8;   // 12800 groups
    int idx = blockIdx.x * blockDim.x + threadIdx.x;
    if (idx >= 2 * PER_MODE) return;
    int mode = idx / PER_MODE;
    int rem  = idx - mode * PER_MODE;
    int col8 = rem & 7;
    int r    = (rem >> 3) & 63;
    int t    = rem >> 9;           // 0..24
    int c    = t % NCHK;
    int s    = t / NCHK;
    int n  = s * 64 + r;
    int k0 = c * 64 + col8 * 8;

    const float* row = nullptr;
    if (n < 300) row = (mode == 0 ? Wenc : Wdec) + (long)n * 300;
    else if (mode == 0 && n < 302) row = Wcls + (long)(n - 300) * 300;

    float v[8];
#pragma unroll
    for (int j = 0; j < 8; j++) v[j] = 0.f;
    if (row) {
        if (k0 + 8 <= 300) {
            float4 f0 = *(const float4*)(row + k0);
            float4 f1 = *(const float4*)(row + k0 + 4);
            v[0]=f0.x; v[1]=f0.y; v[2]=f0.z; v[3]=f0.w;
            v[4]=f1.x; v[5]=f1.y; v[6]=f1.z; v[7]=f1.w;
        } else if (k0 < 300) {
            float4 f0 = *(const float4*)(row + k0);
            v[0]=f0.x; v[1]=f0.y; v[2]=f0.z; v[3]=f0.w;
        }
    }
    int4* gw = (mode == 0) ? g_w1 : g_w2;
    char* base = (char*)gw + (size_t)(s * NCHK + c) * B_CHT_B;
    *(int4*)(base + swz((uint32_t)(r * 128 + (k0 & 63) * 2))) = pack8_bf16(v);
}

// ---------------------------------------------------------------------------
// bf16 HMMA GEMM, cp.async double-buffered, paired-x4 B ldmatrix.
// C[128,64] tile = A[128,320] @ W[64,320]^T, K in 5 chunks of 64.
// mode 1: epilogue -> g_a2 (bf16 swizzled A-layout) + g_logits (+b_cls)
// mode 2: epilogue -> g_cv f32 (+b_dec)
// ---------------------------------------------------------------------------
__global__ __launch_bounds__(256)
void gemm_kernel(const int4* __restrict__ A, const int4* __restrict__ B,
                 const float* __restrict__ bias, const float* __restrict__ bias2,
                 int mode)
{
    __shared__ int4 smem[2 * A_CHT_I4 + 2 * B_CHT_I4];   // 48 KB
    const uint32_t sbase = smem_u32(smem);
    const uint32_t sAoff[2] = { 0u, (uint32_t)A_CHT_B };
    const uint32_t sBoff[2] = { 2u * A_CHT_B, 2u * A_CHT_B + B_CHT_B };

    const int tid  = threadIdx.x;
    const int wid  = tid >> 5;
    const int lane = tid & 31;
    const int mt = blockIdx.y;
    const int ns = blockIdx.x;
    const int mw = wid & 3;          // M quarter (32 rows)
    const int nw = wid >> 2;         // N half   (32 cols)

    float acc[2][4][4];
#pragma unroll
    for (int i = 0; i < 2; i++)
#pragma unroll
        for (int j = 0; j < 4; j++)
#pragma unroll
            for (int q = 0; q < 4; q++) acc[i][j][q] = 0.f;

    const int4* Abase = A + (size_t)mt * NCHK * A_CHT_I4;
    const int4* Bbase = B + (size_t)ns * NCHK * B_CHT_I4;

    // ldmatrix address components
    const uint32_t a_row  = mw * 32 + (lane & 15);
    const uint32_t a_kb   = (lane >> 4) * 16;                      // bytes
    const uint32_t b_row  = nw * 32 + (lane & 7) + ((lane >> 4) << 3);  // paired-x4 rows
    const uint32_t b_kb   = ((lane >> 3) & 1) * 16;                // bytes

#define PREFETCH(c, buf) do {                                                  \
        const int4* _as = Abase + (c) * A_CHT_I4;                              \
        uint32_t _da = sbase + sAoff[buf];                                     \
        _Pragma("unroll")                                                      \
        for (int _i = 0; _i < 4; _i++)                                         \
            cp_async16(_da + (uint32_t)(tid + _i * 256) * 16u, _as + tid + _i * 256); \
        const int4* _bs = Bbase + (c) * B_CHT_I4;                              \
        uint32_t _db = sbase + sBoff[buf];                                     \
        _Pragma("unroll")                                                      \
        for (int _i = 0; _i < 2; _i++)                                         \
            cp_async16(_db + (uint32_t)(tid + _i * 256) * 16u, _bs + tid + _i * 256); \
        cp_commit();                                                           \
    } while (0)

    PREFETCH(0, 0);

    for (int c = 0; c < NCHK; c++) {
        if (c + 1 < NCHK) { PREFETCH(c + 1, (c + 1) & 1); cp_wait1(); }
        else              { cp_wait0(); }
        __syncthreads();

        const uint32_t aB = sbase + sAoff[c & 1];
        const uint32_t bB = sbase + sBoff[c & 1];
#pragma unroll
        for (int ks = 0; ks < 4; ks++) {
            const uint32_t kb = ks * 32;
            uint32_t a[2][4];
#pragma unroll
            for (int fm = 0; fm < 2; fm++)
                ldm_x4(a[fm], aB + swz((a_row + fm * 16) * 128 + kb + a_kb));
#pragma unroll
            for (int p = 0; p < 2; p++) {
                uint32_t bq[4];
                ldm_x4(bq, bB + swz((b_row + p * 16) * 128 + kb + b_kb));
                mma_16816(acc[0][2 * p + 0], a[0], bq + 0);
                mma_16816(acc[1][2 * p + 0], a[1], bq + 0);
                mma_16816(acc[0][2 * p + 1], a[0], bq + 2);
                mma_16816(acc[1][2 * p + 1], a[1], bq + 2);
            }
        }
        __syncthreads();
    }
#undef PREFETCH

    // ---- epilogue ----
#pragma unroll
    for (int fm = 0; fm < 2; fm++) {
#pragma unroll
        for (int fn = 0; fn < 4; fn++) {
            const int n = ns * 64 + nw * 32 + fn * 8 + 2 * (lane & 3);
#pragma unroll
            for (int half = 0; half < 2; half++) {
                const int mrow = mw * 32 + fm * 16 + (lane >> 2) + half * 8;
                const long m = (long)mt * MTILE + mrow;
                float v0 = acc[fm][fn][half * 2 + 0];
                float v1 = acc[fm][fn][half * 2 + 1];
                if (mode == 1) {
                    float b0 = (n < 300) ? bias[n] : ((n == 300) ? bias2[0] : 0.f);
                    float b1 = (n + 1 < 300) ? bias[n + 1] : ((n + 1 == 301) ? bias2[1] : 0.f);
                    v0 += b0; v1 += b1;
                    if (n == 300) {
                        g_logits[m * 2 + 0] = v0;
                        g_logits[m * 2 + 1] = v1;
                    }
                    __nv_bfloat162 h = __floats2bfloat162_rn(v0, v1);
                    char* dst = (char*)g_a2 + (size_t)(mt * NCHK + ns) * A_CHT_B
                                + swz((uint32_t)(mrow * 128 + (n & 63) * 2));
                    *(__nv_bfloat162*)dst = h;
                } else {
                    if (n < 300) {  // n even => n <= 298
                        v0 += bias[n];
                        v1 += bias[n + 1];
                        *(float2*)(g_cv + m * EMBED + n) = make_float2(v0, v1);
                    }
                }
            }
        }
    }
}

// ---------------------------------------------------------------------------
// math helpers
// ---------------------------------------------------------------------------
__device__ __forceinline__ float softplus_f(float x) {
    float ax = fabsf(x);
    float r = log1pf(__expf(-ax));
    return (x > 0.f) ? x + r : r;
}
__device__ __forceinline__ float clip10(float x) { return fminf(fmaxf(x, -10.f), 10.f); }
__device__ __forceinline__ float warp_sum(float v) {
#pragma unroll
    for (int o = 16; o > 0; o >>= 1) v += __shfl_xor_sync(0xffffffffu, v, o);
    return v;
}

// ---------------------------------------------------------------------------
// Score: one warp per sample. All 11 gathered dot-products accumulated with
// full ILP (55 independent float2 loads in flight), reductions at the end.
// ---------------------------------------------------------------------------
__global__ __launch_bounds__(256)
void score_kernel(const int* __restrict__ ctx_ids,
                  const int* __restrict__ neg_ids,
                  const int* __restrict__ party,
                  const float* __restrict__ ctx_emb)
{
    const int warp = threadIdx.x >> 5;
    const int lane = threadIdx.x & 31;
    const int b    = blockIdx.x * 8 + warp;

    __shared__ float s_deno[8];
    __shared__ float s_cono[8];

    float2 cv[5];
    const float2* cvrow = (const float2*)(g_cv + (long)b * EMBED);
#pragma unroll
    for (int j = 0; j < 5; j++) {
        int e2 = lane + j * 32;
        cv[j] = (e2 < 150) ? cvrow[e2] : make_float2(0.f, 0.f);
    }

    const float2* rows[11];
    rows[0] = (const float2*)(ctx_emb + (long)ctx_ids[b] * EMBED);
#pragma unroll
    for (int k = 0; k < K_NEG; k++)
        rows[1 + k] = (const float2*)(ctx_emb + (long)neg_ids[b * K_NEG + k] * EMBED);

    float s[11];
#pragma unroll
    for (int r = 0; r < 11; r++) s[r] = 0.f;

#pragma unroll
    for (int j = 0; j < 5; j++) {
        int e2 = lane + j * 32;
        if (e2 < 150) {
#pragma unroll
            for (int r = 0; r < 11; r++) {
                float2 t = rows[r][e2];
                s[r] = fmaf(cv[j].x, t.x, fmaf(cv[j].y, t.y, s[r]));
            }
        }
    }

#pragma unroll
    for (int r = 0; r < 11; r++) s[r] = warp_sum(s[r]);

    float deno = softplus_f(-clip10(s[0]));
#pragma unroll
    for (int r = 1; r < 11; r++) deno += softplus_f(clip10(s[r]));

    float l0 = g_logits[b * 2 + 0];
    float l1 = g_logits[b * 2 + 1];
    int lab = party[b];
    float nll = softplus_f((lab == 0) ? (l1 - l0) : (l0 - l1));

    if (lane == 0) { s_deno[warp] = deno; s_cono[warp] = nll; }
    __syncthreads();
    if (threadIdx.x == 0) {
        float ds = 0.f, cs = 0.f;
#pragma unroll
        for (int w = 0; w < 8; w++) { ds += s_deno[w]; cs += s_cono[w]; }
        g_partial[blockIdx.x * 2 + 0] = ds;
        g_partial[blockIdx.x * 2 + 1] = cs;
    }
}

// ---------------------------------------------------------------------------
// Finalize
// ---------------------------------------------------------------------------
__global__ __launch_bounds__(1024)
void finalize_kernel(float* __restrict__ out)
{
    __shared__ float sd[1024];
    __shared__ float sc[1024];
    float d = 0.f, c = 0.f;
    for (int i = threadIdx.x; i < NPART; i += 1024) {
        d += g_partial[i * 2 + 0];
        c += g_partial[i * 2 + 1];
    }
    sd[threadIdx.x] = d; sc[threadIdx.x] = c;
    __syncthreads();
    for (int s = 512; s > 0; s >>= 1) {
        if (threadIdx.x < s) {
            sd[threadIdx.x] += sd[threadIdx.x + s];
            sc[threadIdx.x] += sc[threadIdx.x + s];
        }
        __syncthreads();
    }
    if (threadIdx.x == 0) {
        float deno = sd[0] / (float)BATCH;
        float cono = sc[0] / (float)BATCH;
        deno = fminf(fmaxf(deno, EPS_F), 10.f);
        cono = fminf(fmaxf(cono, EPS_F), 10.f);
        out[0] = fmaxf(deno + cono, EPS_F);
        out[1] = deno;
        out[2] = cono;
    }
}

// ---------------------------------------------------------------------------
// kernel_launch
// ---------------------------------------------------------------------------
extern "C" void kernel_launch(void* const* d_in, const int* in_sizes, int n_in,
                              void* d_out, int out_size)
{
    const int*   center_ids = (const int*)  d_in[0];
    const int*   ctx_ids    = (const int*)  d_in[1];
    const int*   neg_ids    = (const int*)  d_in[2];
    const int*   party      = (const int*)  d_in[3];
    const float* center_emb = (const float*)d_in[4];
    const float* ctx_emb    = (const float*)d_in[5];
    const float* W_enc      = (const float*)d_in[6];
    const float* b_enc      = (const float*)d_in[7];
    const float* W_dec      = (const float*)d_in[8];
    const float* b_dec      = (const float*)d_in[9];
    const float* W_cls      = (const float*)d_in[10];
    const float* b_cls      = (const float*)d_in[11];
    float* out = (float*)d_out;

    int4 *a1, *a2, *w1, *w2;
    cudaGetSymbolAddress((void**)&a1, g_a1);
    cudaGetSymbolAddress((void**)&a2, g_a2);
    cudaGetSymbolAddress((void**)&w1, g_w1);
    cudaGetSymbolAddress((void**)&w2, g_w2);

    // prepass conversions
    conv_w_kernel<<<(2 * NSPLIT * NCHK * 64 * 8 + 255) / 256, 256>>>(W_enc, W_cls, W_dec);
    conv_a_kernel<<<BATCH * 40 / 256, 256>>>(center_emb, center_ids);

    // GEMM1: [enc | logits] = gather(center_emb) @ [W_enc; W_cls]^T
    gemm_kernel<<<dim3(NSPLIT, MTILES), 256>>>(a1, w1, b_enc, b_cls, 1);
    // GEMM2: cv = enc @ W_dec^T + b_dec
    gemm_kernel<<<dim3(NSPLIT, MTILES), 256>>>(a2, w2, b_dec, nullptr, 2);

    // scoring + reduction
    score_kernel<<<NPART, 256>>>(ctx_ids, neg_ids, party, ctx_emb);
    finalize_kernel<<<1, 1024>>>(out);
}